// round 3
// baseline (speedup 1.0000x reference)
#include <cuda_runtime.h>
#include <math.h>

// Problem constants
#define Bn 32
#define CIN 96
#define Tt 288
#define Vv 25
#define Ss 3
#define Cc 96
#define VP 28            // padded V for z scratch
#define TTc 32           // t's per CTA (pass 1)
#define NT 9             // 288/32
#define QC 24            // channels per CTA quarter
#define Jn 72            // Ss*QC j's per CTA
#define JR 76            // row stride sWt/sYt
#define XR 52            // duplicated-x row stride (2*25 + 2 pad)
#define AR 56            // duplicated-A row stride

typedef unsigned long long ull;

__device__ float  g_z[(size_t)Bn * Cc * Tt * VP];
__device__ double g_psum[Cc * Bn];
__device__ double g_pss [Cc * Bn];
__device__ float  g_mean[Cc];
__device__ float  g_rstd[Cc];

__device__ __forceinline__ void fma2(ull &d, ull a, ull b) {
    asm("fma.rn.f32x2 %0, %1, %2, %0;" : "+l"(d) : "l"(a), "l"(b));
}
__device__ __forceinline__ float lo2(ull v) { return __uint_as_float((unsigned)(v & 0xffffffffull)); }
__device__ __forceinline__ float hi2(ull v) { return __uint_as_float((unsigned)(v >> 32)); }

// ---------------------------------------------------------------------------
// Pass 1 (pipelined, role-split). Per (b, t-tile, c-quarter h):
//   BIG   (tid 0..125):   y[j][m] = sum_k W[o(j)][k] * xd[k][m]   (+bias)
//   SMALL (tid 128..169): z[c][m] = sum_{s,n} y_prev[s*24+cc][n] * A[s][n][m]
//   PF    (tid 176..255): stream x(t+1) gmem -> sXd[next], duplicated
// One __syncthreads per iteration; sYt and sXd double-buffered.
// smem (floats):
//   sWt [96][76]        7296
//   sYt [2][28][76]     4256
//   sXd [2][96][52]     9984
//   sAd [75][56]        4200
//   sB  [72]              72
//   total 25808 floats = 103232 B  -> 2 CTAs/SM
// ---------------------------------------------------------------------------
__global__ void __launch_bounds__(256, 2)
pass1_kernel(const float* __restrict__ x, const float* __restrict__ A,
             const float* __restrict__ W, const float* __restrict__ bias) {
    extern __shared__ float smem[];
    float* sWt = smem;               //  7296
    float* sYt = smem + 7296;        //  4256 (2 x 2128)
    float* sXd = smem + 11552;       //  9984 (2 x 4992)
    float* sAd = smem + 21536;       //  4200
    float* sB  = smem + 25736;       //    72

    const int tid = threadIdx.x;
    const int t0  = blockIdx.x * TTc;
    const int b   = blockIdx.y;
    const int h   = blockIdx.z;

    // ---- preamble ----
    // W quarter, transposed: sWt[k*76 + j], j = s*24+cc -> o = s*96 + h*24 + cc
    for (int idx = tid; idx < Jn * CIN; idx += 256) {
        int j = idx / CIN, k = idx % CIN;
        int s = j / QC, cc = j % QC;
        sWt[k * JR + j] = W[(s * Cc + h * QC + cc) * CIN + k];
    }
    // A duplicated + padded
    for (int idx = tid; idx < Ss * Vv * VP; idx += 256) {
        int row = idx / VP;          // s*25 + n
        int m   = idx % VP;
        int s = row / Vv, n = row % Vv;
        float a = (m < Vv) ? A[(s * Vv + n) * Vv + m] : 0.0f;
        sAd[row * AR + 2 * m]     = a;
        sAd[row * AR + 2 * m + 1] = a;
    }
    // bias quarter
    for (int idx = tid; idx < Jn; idx += 256) {
        int s = idx / QC, cc = idx % QC;
        sB[idx] = bias[s * Cc + h * QC + cc];
    }
    // zero both x buffers (pads stay zero forever)
    for (int idx = tid; idx < 2 * CIN * XR; idx += 256) sXd[idx] = 0.0f;
    __syncthreads();
    // initial x slice (t0) into buffer 0, duplicated
    for (int idx = tid; idx < CIN * Vv; idx += 256) {
        int i = idx / Vv, n = idx % Vv;
        float v = x[((b * CIN + i) * Tt + t0) * Vv + n];
        sXd[i * XR + 2 * n]     = v;
        sXd[i * XR + 2 * n + 1] = v;
    }
    __syncthreads();

    // role-local mapping
    const int mtB = tid % 7;          // BIG: m-tile
    const int jbB = tid / 7;          // BIG: j-block (0..17) -> 4 j's
    const int stS = tid - 128;        // SMALL
    const int mtS = stS % 7;
    const int cbS = stS / 7;          // 0..5 -> 4 c's

    for (int tt = 0; tt < TTc; tt++) {
        const int t   = t0 + tt;
        const int cur = tt & 1;
        const int nxt = cur ^ 1;

        if (tid < 126) {
            // ---- BIG: y = W^T x (+bias) for t ----
            const int j0 = jbB * 4;
            const int m0 = mtB * 4;
            ull acc[2][4];
#pragma unroll
            for (int p = 0; p < 2; p++)
#pragma unroll
                for (int q = 0; q < 4; q++) acc[p][q] = 0ull;

            const float* wp = sWt + j0;
            const float* xp = sXd + cur * (CIN * XR) + 2 * m0;
#pragma unroll 4
            for (int k = 0; k < CIN; k++) {
                ulonglong2 w  = *(const ulonglong2*)(wp);      // j0..j0+3
                ulonglong2 x0 = *(const ulonglong2*)(xp);      // m0,m0+1 dup
                ulonglong2 x1 = *(const ulonglong2*)(xp + 4);  // m0+2,m0+3 dup
                fma2(acc[0][0], w.x, x0.x); fma2(acc[0][1], w.x, x0.y);
                fma2(acc[0][2], w.x, x1.x); fma2(acc[0][3], w.x, x1.y);
                fma2(acc[1][0], w.y, x0.x); fma2(acc[1][1], w.y, x0.y);
                fma2(acc[1][2], w.y, x1.x); fma2(acc[1][3], w.y, x1.y);
                wp += JR;
                xp += XR;
            }
            const float b0 = sB[j0],     b1 = sB[j0 + 1];
            const float b2 = sB[j0 + 2], b3 = sB[j0 + 3];
            float* yb = sYt + cur * (VP * JR);
#pragma unroll
            for (int q = 0; q < 4; q++) {
                float4 v;
                v.x = lo2(acc[0][q]) + b0;
                v.y = hi2(acc[0][q]) + b1;
                v.z = lo2(acc[1][q]) + b2;
                v.w = hi2(acc[1][q]) + b3;
                *(float4*)(yb + (m0 + q) * JR + j0) = v;
            }
        } else if (tid >= 128 && tid < 170) {
            // ---- SMALL: z for t-1 from previous sYt buffer ----
            if (tt > 0) {
                const int c0 = cbS * 4;
                const int m0 = mtS * 4;
                ull acc[2][4];
#pragma unroll
                for (int p = 0; p < 2; p++)
#pragma unroll
                    for (int q = 0; q < 4; q++) acc[p][q] = 0ull;
                const float* ybuf = sYt + nxt * (VP * JR);
#pragma unroll
                for (int s = 0; s < Ss; s++) {
                    const float* yrow = ybuf + s * QC + c0;
                    const float* arow = sAd + s * (Vv * AR) + 2 * m0;
#pragma unroll 5
                    for (int n = 0; n < Vv; n++) {
                        ulonglong2 yy = *(const ulonglong2*)(yrow + n * JR);
                        ulonglong2 a0 = *(const ulonglong2*)(arow + n * AR);
                        ulonglong2 a1 = *(const ulonglong2*)(arow + n * AR + 4);
                        fma2(acc[0][0], yy.x, a0.x); fma2(acc[0][1], yy.x, a0.y);
                        fma2(acc[0][2], yy.x, a1.x); fma2(acc[0][3], yy.x, a1.y);
                        fma2(acc[1][0], yy.y, a0.x); fma2(acc[1][1], yy.y, a0.y);
                        fma2(acc[1][2], yy.y, a1.x); fma2(acc[1][3], yy.y, a1.y);
                    }
                }
                const int cglob = h * QC + c0;
                const size_t cstride = (size_t)Tt * VP;
                float* zb = g_z + ((size_t)(b * Cc + cglob) * Tt + (t - 1)) * VP + m0;
                float4 v;
                v.x = lo2(acc[0][0]); v.y = lo2(acc[0][1]); v.z = lo2(acc[0][2]); v.w = lo2(acc[0][3]);
                *(float4*)(zb) = v;
                v.x = hi2(acc[0][0]); v.y = hi2(acc[0][1]); v.z = hi2(acc[0][2]); v.w = hi2(acc[0][3]);
                *(float4*)(zb + cstride) = v;
                v.x = lo2(acc[1][0]); v.y = lo2(acc[1][1]); v.z = lo2(acc[1][2]); v.w = lo2(acc[1][3]);
                *(float4*)(zb + 2 * cstride) = v;
                v.x = hi2(acc[1][0]); v.y = hi2(acc[1][1]); v.z = hi2(acc[1][2]); v.w = hi2(acc[1][3]);
                *(float4*)(zb + 3 * cstride) = v;
            }
        } else if (tid >= 176) {
            // ---- PF: stream x(t+1) into sXd[nxt], duplicated ----
            if (tt + 1 < TTc) {
                const int tn = t + 1;
                int idx = tid - 176;           // 0..79
                int i = idx / Vv, n = idx % Vv;
                float* xb = sXd + nxt * (CIN * XR);
                const float* xg = x + ((size_t)b * CIN * Tt + (size_t)tn) * Vv;
#pragma unroll
                for (int r = 0; r < 30; r++) {
                    float v = xg[i * (Tt * Vv) + n];
                    float2 d; d.x = v; d.y = v;
                    *(float2*)(xb + i * XR + 2 * n) = d;
                    // idx += 80  ->  i += 3, n += 5 with carry
                    i += 3; n += 5;
                    if (n >= Vv) { n -= Vv; i += 1; }
                }
            }
        }
        __syncthreads();
    }

    // SMALL epilogue for the final t (y sits in buffer (TTc-1)&1 = 1)
    if (tid >= 128 && tid < 170) {
        const int t = t0 + TTc - 1;
        const int c0 = cbS * 4;
        const int m0 = mtS * 4;
        ull acc[2][4];
#pragma unroll
        for (int p = 0; p < 2; p++)
#pragma unroll
            for (int q = 0; q < 4; q++) acc[p][q] = 0ull;
        const float* ybuf = sYt + 1 * (VP * JR);
#pragma unroll
        for (int s = 0; s < Ss; s++) {
            const float* yrow = ybuf + s * QC + c0;
            const float* arow = sAd + s * (Vv * AR) + 2 * m0;
#pragma unroll 5
            for (int n = 0; n < Vv; n++) {
                ulonglong2 yy = *(const ulonglong2*)(yrow + n * JR);
                ulonglong2 a0 = *(const ulonglong2*)(arow + n * AR);
                ulonglong2 a1 = *(const ulonglong2*)(arow + n * AR + 4);
                fma2(acc[0][0], yy.x, a0.x); fma2(acc[0][1], yy.x, a0.y);
                fma2(acc[0][2], yy.x, a1.x); fma2(acc[0][3], yy.x, a1.y);
                fma2(acc[1][0], yy.y, a0.x); fma2(acc[1][1], yy.y, a0.y);
                fma2(acc[1][2], yy.y, a1.x); fma2(acc[1][3], yy.y, a1.y);
            }
        }
        const int cglob = h * QC + c0;
        const size_t cstride = (size_t)Tt * VP;
        float* zb = g_z + ((size_t)(b * Cc + cglob) * Tt + t) * VP + m0;
        float4 v;
        v.x = lo2(acc[0][0]); v.y = lo2(acc[0][1]); v.z = lo2(acc[0][2]); v.w = lo2(acc[0][3]);
        *(float4*)(zb) = v;
        v.x = hi2(acc[0][0]); v.y = hi2(acc[0][1]); v.z = hi2(acc[0][2]); v.w = hi2(acc[0][3]);
        *(float4*)(zb + cstride) = v;
        v.x = lo2(acc[1][0]); v.y = lo2(acc[1][1]); v.z = lo2(acc[1][2]); v.w = lo2(acc[1][3]);
        *(float4*)(zb + 2 * cstride) = v;
        v.x = hi2(acc[1][0]); v.y = hi2(acc[1][1]); v.z = hi2(acc[1][2]); v.w = hi2(acc[1][3]);
        *(float4*)(zb + 3 * cstride) = v;
    }
}

// ---------------------------------------------------------------------------
// Pass 2a: per-(c,b) plane partial BN stats over windowed z.
// ---------------------------------------------------------------------------
__global__ void __launch_bounds__(256)
pass2a_kernel() {
    const int c = blockIdx.x;
    const int b = blockIdx.y;
    const int tid = threadIdx.x;
    __shared__ float sP[Tt * VP];
    __shared__ double red[512];

    const float* src = g_z + (size_t)(b * Cc + c) * Tt * VP;
    for (int i = tid; i < Tt * VP; i += 256) sP[i] = src[i];
    __syncthreads();

    double s = 0.0, q = 0.0;
    int t = tid / Vv, m = tid % Vv;
    // 288*25 = 7200 = 28*256 + 32 -> 29 steps, last partial
    for (int it = 0; it < 29; it++) {
        if (t < Tt) {
            float v = 0.0f;
#pragma unroll
            for (int k = -2; k <= 2; k++) {
                int tk = t + k;
                if (tk >= 0 && tk < Tt) v += sP[tk * VP + m];
            }
            v *= 0.2f;
            s += (double)v;
            q += (double)v * (double)v;
        }
        t += 10; m += 6;                 // += 256
        if (m >= Vv) { m -= Vv; t += 1; }
    }
    red[tid] = s; red[256 + tid] = q;
    __syncthreads();
    for (int s2 = 128; s2 > 0; s2 >>= 1) {
        if (tid < s2) {
            red[tid] += red[tid + s2];
            red[256 + tid] += red[256 + tid + s2];
        }
        __syncthreads();
    }
    if (tid == 0) {
        g_psum[c * Bn + b] = red[0];
        g_pss [c * Bn + b] = red[256];
    }
}

// ---------------------------------------------------------------------------
// Pass 2b: reduce 32 partials per channel -> mean/rstd
// ---------------------------------------------------------------------------
__global__ void __launch_bounds__(32)
pass2b_kernel() {
    const int c = blockIdx.x;
    const int lane = threadIdx.x;
    double s = g_psum[c * Bn + lane];
    double q = g_pss [c * Bn + lane];
#pragma unroll
    for (int o = 16; o > 0; o >>= 1) {
        s += __shfl_down_sync(0xffffffffu, s, o);
        q += __shfl_down_sync(0xffffffffu, q, o);
    }
    if (lane == 0) {
        const double N = (double)Bn * Tt * Vv;
        double mean = s / N;
        double var  = q / N - mean * mean;
        g_mean[c] = (float)mean;
        g_rstd[c] = (float)(1.0 / sqrt(var + 1e-5));
    }
}

// ---------------------------------------------------------------------------
// Pass 3: window-avg + normalize + affine + relu
// ---------------------------------------------------------------------------
__global__ void __launch_bounds__(256)
pass3_kernel(const float* __restrict__ gamma, const float* __restrict__ beta,
             float* __restrict__ out) {
    const int c = blockIdx.x;
    const int b = blockIdx.y;
    const int tid = threadIdx.x;
    __shared__ float sP[Tt * VP];

    const float* src = g_z + (size_t)(b * Cc + c) * Tt * VP;
    for (int i = tid; i < Tt * VP; i += 256) sP[i] = src[i];
    __syncthreads();

    const float mean = g_mean[c];
    const float rstd = g_rstd[c];
    const float sc = rstd * gamma[c];
    const float sh = beta[c] - mean * sc;

    float* dst = out + (size_t)(b * Cc + c) * Tt * Vv;
    int t = tid / Vv, m = tid % Vv;
    int i = tid;
    for (int it = 0; it < 29; it++) {
        if (t < Tt) {
            float v = 0.0f;
#pragma unroll
            for (int k = -2; k <= 2; k++) {
                int tk = t + k;
                if (tk >= 0 && tk < Tt) v += sP[tk * VP + m];
            }
            v *= 0.2f;
            float o = fmaf(v, sc, sh);
            dst[i] = fmaxf(o, 0.0f);
        }
        t += 10; m += 6; i += 256;
        if (m >= Vv) { m -= Vv; t += 1; }
    }
}

// ---------------------------------------------------------------------------
extern "C" void kernel_launch(void* const* d_in, const int* in_sizes, int n_in,
                              void* d_out, int out_size) {
    const float* x     = (const float*)d_in[0];
    const float* A     = (const float*)d_in[1];
    const float* W     = (const float*)d_in[2];
    const float* bias  = (const float*)d_in[3];
    const float* gamma = (const float*)d_in[4];
    const float* beta  = (const float*)d_in[5];
    float* out = (float*)d_out;

    const int smem1 = 25808 * 4;   // 103232 bytes
    cudaFuncSetAttribute(pass1_kernel, cudaFuncAttributeMaxDynamicSharedMemorySize, smem1);

    pass1_kernel<<<dim3(NT, Bn, 4), 256, smem1>>>(x, A, W, bias);
    pass2a_kernel<<<dim3(Cc, Bn), 256>>>();
    pass2b_kernel<<<Cc, 32>>>();
    pass3_kernel<<<dim3(Cc, Bn), 256>>>(gamma, beta, out);
}